// round 5
// baseline (speedup 1.0000x reference)
#include <cuda_runtime.h>
#include <cstdint>
#include <cstddef>

// Ridge_51178830299316 — rank-2 RLS (Woodbury) with 2D-tiled M, round 5.
//
// Bottleneck model (fits rounds 1-3 exactly): shared-memory crossbar
// lane-bytes. Old layout: each P thread owned a 1x32 row-slice of M and
// loaded 64 lane-words/point -> 128 KB/point/SM -> ~1024 cyc/point.
// New layout: each P thread owns a 4x8 TILE of M:
//   rg = tid>>4 (rows 4rg..4rg+3), cg = tid&15 (cols 8cg..8cg+7)
// Per iteration (2 points) it loads only: au[4], bu[4] (row side),
// pc[8], vc[8], x0[8], x1[8] (col side) = 40 lane-words (vs 128).
// Row-sums of the two matvecs are reduced across the 16 lanes sharing a
// row-group via shfl.xor (off 1,2,4,8) — shuffle network, not crossbar —
// and stored by one lane per 16-group as a float4.
// S warp (tid 512..543) is unchanged from the passing round-3 kernel,
// except partials arrive pre-reduced (1 float4 per 4 rows per matvec).

#define BATCH 32
#define NPTS  256
#define DIM   128
#define PTHREADS 512
#define TOT   544
#define NBLK  128            // blocks of 2 steps (x padded with 2 zero rows)

#define FMA2(d, a, bb, c) \
    asm("fma.rn.f32x2 %0, %1, %2, %3;" : "=l"(d) : "l"(a), "l"(bb), "l"(c))

struct SMLayout {
    float xs[NPTS + 2][DIM];     // padded with 2 zero rows
    float ts[NPTS];
    float part[2][2][DIM];       // [buf][matvec 0/1][row] — fully reduced
    float pc[2][DIM];            // column-side p
    float vc[2][DIM];            // column-side v
    float au[2][DIM];            // inv1 * p  (row-side)
    float bu[2][DIM];            // inv2 * v  (row-side)
};

__device__ __forceinline__ float ull_lo(unsigned long long x) {
    return __uint_as_float((unsigned)x);
}
__device__ __forceinline__ float ull_hi(unsigned long long x) {
    return __uint_as_float((unsigned)(x >> 32));
}
__device__ __forceinline__ unsigned long long pack2(float f) {
    unsigned long long r;
    asm("mov.b64 %0, {%1, %1};" : "=l"(r) : "r"(__float_as_uint(f)));
    return r;
}

__global__ void __launch_bounds__(TOT, 1)
ridge_rls2t_kernel(const float* __restrict__ data,
                   const float* __restrict__ targets,
                   float* __restrict__ out)
{
    extern __shared__ char smem_raw[];
    SMLayout& sm = *reinterpret_cast<SMLayout*>(smem_raw);
    const int tid = threadIdx.x;
    const int b   = blockIdx.x;

    // ---- Stage inputs ----
    {
        const float4* src = reinterpret_cast<const float4*>(data + (size_t)b * NPTS * DIM);
        float4* dst = reinterpret_cast<float4*>(&sm.xs[0][0]);
        for (int idx = tid; idx < NPTS * DIM / 4; idx += TOT)
            dst[idx] = src[idx];
        if (tid < 2 * DIM / 4)
            reinterpret_cast<float4*>(&sm.xs[NPTS][0])[tid] =
                make_float4(0.f, 0.f, 0.f, 0.f);
        if (tid < NPTS / 4)
            reinterpret_cast<float4*>(sm.ts)[tid] =
                reinterpret_cast<const float4*>(targets + (size_t)b * NPTS)[tid];
    }
    __syncthreads();

    // ---- Prologue: raw matvecs of block 0 are I*x_0, I*x_1 ----
    if (tid < DIM) {
        sm.part[0][0][tid] = sm.xs[0][tid];
        sm.part[0][1][tid] = sm.xs[1][tid];
        sm.pc[0][tid] = 0.f;  sm.vc[0][tid] = 0.f;   // block -1 update = 0
        sm.au[0][tid] = 0.f;  sm.bu[0][tid] = 0.f;
    }
    if (tid == 0) out[(size_t)b * NPTS] = 0.f;
    __syncthreads();

    // ---- P persistent state: 4x8 tile of M = I as packed f32x2 ----
    const int rg = tid >> 4;      // row group: rows 4rg..4rg+3
    const int cg = tid & 15;      // col group: cols 8cg..8cg+7
    unsigned long long m2[4][4];  // [row][packed col pair]
    if (tid < PTHREADS) {
        #pragma unroll
        for (int r = 0; r < 4; r++) {
            #pragma unroll
            for (int c = 0; c < 4; c++) {
                const int grow = 4 * rg + r;
                unsigned lo = (grow == 8 * cg + 2 * c)     ? 0x3f800000u : 0u;
                unsigned hi = (grow == 8 * cg + 2 * c + 1) ? 0x3f800000u : 0u;
                m2[r][c] = ((unsigned long long)hi << 32) | lo;
            }
        }
    }

    // ---- S persistent state (4 rows per lane) ----
    const int lane = tid - PTHREADS;
    const int i0   = lane * 4;
    float w0 = 0.f, w1 = 0.f, w2 = 0.f, w3 = 0.f;
    float pp0 = 0.f, pp1 = 0.f, pp2 = 0.f, pp3 = 0.f;
    float pv0 = 0.f, pv1 = 0.f, pv2 = 0.f, pv3 = 0.f;
    float cp0 = 0.f, cv0 = 0.f, cp1 = 0.f, cv1 = 0.f;

    int buf = 0;
    #pragma unroll 1
    for (int t = 0; t < NBLK; t++) {
        const int k = 2 * t;
        if (tid < PTHREADS) {
            // ===== P: rank-2 update (prev block) fused with 2 matvecs =====
            const float4 a1 = *reinterpret_cast<const float4*>(&sm.au[buf][rg * 4]);
            const float4 a2 = *reinterpret_cast<const float4*>(&sm.bu[buf][rg * 4]);
            const ulonglong2 v1a = reinterpret_cast<const ulonglong2*>(&sm.pc[buf][cg * 8])[0];
            const ulonglong2 v1b = reinterpret_cast<const ulonglong2*>(&sm.pc[buf][cg * 8])[1];
            const ulonglong2 v2a = reinterpret_cast<const ulonglong2*>(&sm.vc[buf][cg * 8])[0];
            const ulonglong2 v2b = reinterpret_cast<const ulonglong2*>(&sm.vc[buf][cg * 8])[1];
            const ulonglong2 x0a = reinterpret_cast<const ulonglong2*>(&sm.xs[k + 2][cg * 8])[0];
            const ulonglong2 x0b = reinterpret_cast<const ulonglong2*>(&sm.xs[k + 2][cg * 8])[1];
            const ulonglong2 x1a = reinterpret_cast<const ulonglong2*>(&sm.xs[k + 3][cg * 8])[0];
            const ulonglong2 x1b = reinterpret_cast<const ulonglong2*>(&sm.xs[k + 3][cg * 8])[1];

            const unsigned long long v1c[4] = { v1a.x, v1a.y, v1b.x, v1b.y };
            const unsigned long long v2c[4] = { v2a.x, v2a.y, v2b.x, v2b.y };
            const unsigned long long x0c[4] = { x0a.x, x0a.y, x0b.x, x0b.y };
            const unsigned long long x1c[4] = { x1a.x, x1a.y, x1b.x, x1b.y };
            const unsigned long long A1[4] = { pack2(-a1.x), pack2(-a1.y),
                                               pack2(-a1.z), pack2(-a1.w) };
            const unsigned long long A2[4] = { pack2(-a2.x), pack2(-a2.y),
                                               pack2(-a2.z), pack2(-a2.w) };

            unsigned long long acc0[4] = {0ull, 0ull, 0ull, 0ull};
            unsigned long long acc1[4] = {0ull, 0ull, 0ull, 0ull};
            #pragma unroll
            for (int r = 0; r < 4; r++) {
                #pragma unroll
                for (int c = 0; c < 4; c++) {
                    FMA2(m2[r][c], A1[r], v1c[c], m2[r][c]);
                    FMA2(m2[r][c], A2[r], v2c[c], m2[r][c]);
                    FMA2(acc0[r], m2[r][c], x0c[c], acc0[r]);
                    FMA2(acc1[r], m2[r][c], x1c[c], acc1[r]);
                }
            }
            float s0[4], s1[4];
            #pragma unroll
            for (int r = 0; r < 4; r++) {
                s0[r] = ull_lo(acc0[r]) + ull_hi(acc0[r]);
                s1[r] = ull_lo(acc1[r]) + ull_hi(acc1[r]);
            }
            // reduce across the 16 lanes sharing this row group
            #pragma unroll
            for (int off = 1; off < 16; off <<= 1) {
                #pragma unroll
                for (int r = 0; r < 4; r++) {
                    s0[r] += __shfl_xor_sync(0xffffffffu, s0[r], off);
                    s1[r] += __shfl_xor_sync(0xffffffffu, s1[r], off);
                }
            }
            if (cg == 0) {
                *reinterpret_cast<float4*>(&sm.part[buf ^ 1][0][rg * 4]) =
                    make_float4(s0[0], s0[1], s0[2], s0[3]);
                *reinterpret_cast<float4*>(&sm.part[buf ^ 1][1][rg * 4]) =
                    make_float4(s1[0], s1[1], s1[2], s1[3]);
            }
        } else {
            // ===== S: correct staleness, 10-value reduce, scalar math =====
            const float4 pr = *reinterpret_cast<const float4*>(&sm.part[buf][0][i0]);
            const float4 qr = *reinterpret_cast<const float4*>(&sm.part[buf][1][i0]);
            const float p0 = pr.x - cp0 * pp0 - cv0 * pv0;
            const float p1 = pr.y - cp0 * pp1 - cv0 * pv1;
            const float p2 = pr.z - cp0 * pp2 - cv0 * pv2;
            const float p3 = pr.w - cp0 * pp3 - cv0 * pv3;
            const float q0 = qr.x - cp1 * pp0 - cv1 * pv0;
            const float q1 = qr.y - cp1 * pp1 - cv1 * pv1;
            const float q2 = qr.z - cp1 * pp2 - cv1 * pv2;
            const float q3 = qr.w - cp1 * pp3 - cv1 * pv3;

            const float4 xk  = *reinterpret_cast<const float4*>(&sm.xs[k][i0]);
            const float4 xk1 = *reinterpret_cast<const float4*>(&sm.xs[k + 1][i0]);
            const float4 xk2 = *reinterpret_cast<const float4*>(&sm.xs[k + 2][i0]);
            const float4 xk3 = *reinterpret_cast<const float4*>(&sm.xs[k + 3][i0]);

            float s1v = (xk.x  * p0 + xk.y  * p1) + (xk.z  * p2 + xk.w  * p3);
            float cS  = (xk.x  * q0 + xk.y  * q1) + (xk.z  * q2 + xk.w  * q3);
            float s2  = (xk1.x * q0 + xk1.y * q1) + (xk1.z * q2 + xk1.w * q3);
            float ew0 = (xk.x  * w0 + xk.y  * w1) + (xk.z  * w2 + xk.w  * w3);
            float ew1 = (xk1.x * w0 + xk1.y * w1) + (xk1.z * w2 + xk1.w * w3);
            float ew2 = (xk2.x * w0 + xk2.y * w1) + (xk2.z * w2 + xk2.w * w3);
            float d1  = (xk2.x * p0 + xk2.y * p1) + (xk2.z * p2 + xk2.w * p3);
            float d2  = (xk2.x * q0 + xk2.y * q1) + (xk2.z * q2 + xk2.w * q3);
            float d3  = (xk3.x * p0 + xk3.y * p1) + (xk3.z * p2 + xk3.w * p3);
            float d4  = (xk3.x * q0 + xk3.y * q1) + (xk3.z * q2 + xk3.w * q3);

            #pragma unroll
            for (int off = 16; off > 0; off >>= 1) {
                s1v += __shfl_xor_sync(0xffffffffu, s1v, off);
                cS  += __shfl_xor_sync(0xffffffffu, cS,  off);
                s2  += __shfl_xor_sync(0xffffffffu, s2,  off);
                ew0 += __shfl_xor_sync(0xffffffffu, ew0, off);
                ew1 += __shfl_xor_sync(0xffffffffu, ew1, off);
                ew2 += __shfl_xor_sync(0xffffffffu, ew2, off);
                d1  += __shfl_xor_sync(0xffffffffu, d1,  off);
                d2  += __shfl_xor_sync(0xffffffffu, d2,  off);
                d3  += __shfl_xor_sync(0xffffffffu, d3,  off);
                d4  += __shfl_xor_sync(0xffffffffu, d4,  off);
            }

            const float inv1  = 1.0f / (1.0f + s1v);
            const float coef0 = (sm.ts[k] - ew0) * inv1;
            const float cc    = cS * inv1;
            const float t2    = s2 - cS * cc;
            const float inv2  = 1.0f / (1.0f + t2);
            const float pred1 = fmaf(coef0, cS, ew1);
            const float coef1 = (sm.ts[k + 1] - pred1) * inv2;
            const float pred2 = ew2 + coef0 * d1 + coef1 * (d2 - cc * d1);

            const float nv0 = q0 - cc * p0, nv1 = q1 - cc * p1;
            const float nv2 = q2 - cc * p2, nv3 = q3 - cc * p3;
            w0 += coef0 * p0 + coef1 * nv0;
            w1 += coef0 * p1 + coef1 * nv1;
            w2 += coef0 * p2 + coef1 * nv2;
            w3 += coef0 * p3 + coef1 * nv3;

            const int nb = buf ^ 1;
            *reinterpret_cast<float4*>(&sm.pc[nb][i0]) = make_float4(p0, p1, p2, p3);
            *reinterpret_cast<float4*>(&sm.vc[nb][i0]) = make_float4(nv0, nv1, nv2, nv3);
            *reinterpret_cast<float4*>(&sm.au[nb][i0]) =
                make_float4(inv1 * p0, inv1 * p1, inv1 * p2, inv1 * p3);
            *reinterpret_cast<float4*>(&sm.bu[nb][i0]) =
                make_float4(inv2 * nv0, inv2 * nv1, inv2 * nv2, inv2 * nv3);

            if (lane == 0) {
                out[(size_t)b * NPTS + k + 1] = pred1;
                if (k + 2 < NPTS) out[(size_t)b * NPTS + k + 2] = pred2;
            }

            pp0 = p0; pp1 = p1; pp2 = p2; pp3 = p3;
            pv0 = nv0; pv1 = nv1; pv2 = nv2; pv3 = nv3;
            cp0 = inv1 * d1;  cv0 = inv2 * (d2 - cc * d1);
            cp1 = inv1 * d3;  cv1 = inv2 * (d4 - cc * d3);
        }
        __syncthreads();
        buf ^= 1;
    }
}

extern "C" void kernel_launch(void* const* d_in, const int* in_sizes, int n_in,
                              void* d_out, int out_size)
{
    const float* data    = (const float*)d_in[0];   // [32, 256, 128] f32
    const float* targets = (const float*)d_in[1];   // [32, 256]      f32
    float* out = (float*)d_out;                     // [32, 256]      f32

    const size_t smem_bytes = sizeof(SMLayout);
    cudaFuncSetAttribute(ridge_rls2t_kernel,
                         cudaFuncAttributeMaxDynamicSharedMemorySize,
                         (int)smem_bytes);
    ridge_rls2t_kernel<<<BATCH, TOT, smem_bytes>>>(data, targets, out);
}